// round 9
// baseline (speedup 1.0000x reference)
#include <cuda_runtime.h>
#include <cuda_fp16.h>
#include <stdint.h>

#define SQ 2048
#define DH 64
#define NH_ 16
#define NB_ 4
#define KT 32
#define NTILES (SQ/KT)
#define OUT_ELEMS (NB_*NH_*SQ*DH)
#define RSTRIDE 144
#define QSCALE 0.18033688011112042f   // 0.125 * log2(e); exp(s) = exp2(S)

__device__ unsigned g_maskbits[(size_t)NB_ * SQ * (SQ / 32)];   // 2 MB

// smem: K dbuf [0,9216), V dbuf [9216,18432). Q staged over [0,18432) in prologue.
#define SKH(bf) ((bf)*4608)
#define SVH(bf) (9216 + (bf)*4608)
#define SMEM_F 18432

// ---------------- PTX helpers ----------------
__device__ __forceinline__ void ldsm4(uint32_t* r, uint32_t a) {
    asm volatile("ldmatrix.sync.aligned.m8n8.x4.shared.b16 {%0,%1,%2,%3}, [%4];"
                 : "=r"(r[0]), "=r"(r[1]), "=r"(r[2]), "=r"(r[3]) : "r"(a));
}
__device__ __forceinline__ void ldsm4t(uint32_t* r, uint32_t a) {
    asm volatile("ldmatrix.sync.aligned.m8n8.x4.trans.shared.b16 {%0,%1,%2,%3}, [%4];"
                 : "=r"(r[0]), "=r"(r[1]), "=r"(r[2]), "=r"(r[3]) : "r"(a));
}
__device__ __forceinline__ void mma16816(float* c, const uint32_t* a, const uint32_t* b) {
    asm volatile("mma.sync.aligned.m16n8k16.row.col.f32.f16.f16.f32 "
                 "{%0,%1,%2,%3}, {%4,%5,%6,%7}, {%8,%9}, {%0,%1,%2,%3};"
                 : "+f"(c[0]), "+f"(c[1]), "+f"(c[2]), "+f"(c[3])
                 : "r"(a[0]), "r"(a[1]), "r"(a[2]), "r"(a[3]), "r"(b[0]), "r"(b[1]));
}
__device__ __forceinline__ uint32_t packh(float x, float y) {
    __half2 h = __halves2half2(__float2half_rn(x), __float2half_rn(y));
    return *reinterpret_cast<uint32_t*>(&h);
}
__device__ __forceinline__ uint2 cvt_f4(float4 x) {
    return make_uint2(packh(x.x, x.y), packh(x.z, x.w));
}
__device__ __forceinline__ void sts_u2(char* sm, int off, int lin, uint2 v) {
    uint32_t a = (uint32_t)(lin >> 4) * RSTRIDE + (uint32_t)(lin & 15) * 8;
    *reinterpret_cast<uint2*>(sm + off + a) = v;
}

// ---------------- mask bit-pack ----------------
__global__ void maskpack_kernel(const int* __restrict__ mask) {
    int gwarp = blockIdx.x * 8 + (threadIdx.x >> 5);
    int lane = threadIdx.x & 31;
    size_t base = (size_t)gwarp * 128;
    unsigned b0 = __ballot_sync(0xffffffffu, mask[base + lane] != 0);
    unsigned b1 = __ballot_sync(0xffffffffu, mask[base + 32 + lane] != 0);
    unsigned b2 = __ballot_sync(0xffffffffu, mask[base + 64 + lane] != 0);
    unsigned b3 = __ballot_sync(0xffffffffu, mask[base + 96 + lane] != 0);
    if (lane == 0)
        *reinterpret_cast<uint4*>(&g_maskbits[(size_t)gwarp * 4]) = make_uint4(b0, b1, b2, b3);
}

// ---------------- fused: phase1 lsum, phase2 attn + PV ----------------
__global__ __launch_bounds__(256, 2)
void sdpa_fused(const float* __restrict__ qg, const float* __restrict__ kg,
                const float* __restrict__ vg, float* __restrict__ outg)
{
    extern __shared__ char sm[];
    const uint32_t sb = (uint32_t)__cvta_generic_to_shared(sm);
    const int tid = threadIdx.x, warp = tid >> 5, lane = tid & 31;
    const int g = lane >> 2, t4 = lane & 3;
    const int qt = blockIdx.x, h = blockIdx.y, b = blockIdx.z;
    const int q0 = qt * 128;
    const size_t bh = (size_t)(b * NH_ + h);
    const float* qb = qg + (bh * SQ + (size_t)q0) * DH;
    const float4* ks = reinterpret_cast<const float4*>(kg + bh * SQ * DH);
    const float4* vs = reinterpret_cast<const float4*>(vg + bh * SQ * DH);
    const int r0 = warp * 16 + g, r1 = r0 + 8;

    // ---- prologue: stage Q (scaled) -> smem, ldsm into registers, release ----
#pragma unroll
    for (int i = 0; i < 8; i++) {
        int lin = i * 256 + tid;
        float4 x = reinterpret_cast<const float4*>(qb)[lin];
        x.x *= QSCALE; x.y *= QSCALE; x.z *= QSCALE; x.w *= QSCALE;
        sts_u2(sm, 0, lin, cvt_f4(x));
    }
    __syncthreads();
    const uint32_t qHaddr = sb + (uint32_t)(warp * 16 + (lane & 15)) * RSTRIDE
                          + (uint32_t)(lane >> 4) * 16;
    uint32_t q00[4], q01[4], q10[4], q11[4];   // [kp][frag]: k0-15,16-31,32-47,48-63
    ldsm4(q00, qHaddr);
    ldsm4(q01, qHaddr + 32);
    ldsm4(q10, qHaddr + 64);
    ldsm4(q11, qHaddr + 96);
    __syncthreads();   // Q staging consumed; smem now free for K/V buffers

    const uint32_t kfoff = (uint32_t)(lane & 7) * RSTRIDE + (uint32_t)(lane >> 3) * 16;
    const uint32_t vfoff = (uint32_t)(8 * (lane >> 3) + (lane & 7)) * RSTRIDE;
    const unsigned* mw0 = &g_maskbits[((size_t)b * SQ + q0 + r0) * (SQ / 32)];
    const unsigned* mw1 = &g_maskbits[((size_t)b * SQ + q0 + r1) * (SQ / 32)];

    // =============== PHASE 1: lsum ===============
    uint2 ku0 = cvt_f4(ks[tid]), ku1 = cvt_f4(ks[256 + tid]);
    sts_u2(sm, SKH(0), tid, ku0);
    sts_u2(sm, SKH(0), 256 + tid, ku1);

    float lsum0 = 0.0f, lsum1 = 0.0f;
    for (int t = 0; t < NTILES; t++) {
        const int cur = t & 1;
        unsigned w0 = mw0[t], w1 = mw1[t];
        if (t + 1 < NTILES) {
            ku0 = cvt_f4(ks[(t + 1) * 512 + tid]);
            ku1 = cvt_f4(ks[(t + 1) * 512 + 256 + tid]);
        }
        __syncthreads();

        float S[4][4];
#pragma unroll
        for (int ng = 0; ng < 4; ng++)
#pragma unroll
            for (int j = 0; j < 4; j++) S[ng][j] = 0.0f;

#pragma unroll
        for (int kp = 0; kp < 2; kp++) {
#pragma unroll
            for (int ng = 0; ng < 4; ng++) {
                uint32_t kh[4];
                ldsm4(kh, sb + SKH(cur) + (uint32_t)(ng * 8) * RSTRIDE + kp * 64 + kfoff);
                mma16816(S[ng], kp ? q10 : q00, kh + 0);
                mma16816(S[ng], kp ? q11 : q01, kh + 2);
            }
        }

#pragma unroll
        for (int ng = 0; ng < 4; ng++) {
            int j = 8 * ng + 2 * t4;
            lsum0 += (((w0 >> j) & 1u)       ? exp2f(S[ng][0]) : 0.0f)
                   + (((w0 >> (j + 1)) & 1u) ? exp2f(S[ng][1]) : 0.0f);
            lsum1 += (((w1 >> j) & 1u)       ? exp2f(S[ng][2]) : 0.0f)
                   + (((w1 >> (j + 1)) & 1u) ? exp2f(S[ng][3]) : 0.0f);
        }

        if (t + 1 < NTILES) {
            const int nxt = cur ^ 1;
            sts_u2(sm, SKH(nxt), tid, ku0);
            sts_u2(sm, SKH(nxt), 256 + tid, ku1);
        }
    }
    __syncthreads();   // all reads of buffers done before phase-2 restores

    lsum0 += __shfl_xor_sync(0xffffffffu, lsum0, 1);
    lsum0 += __shfl_xor_sync(0xffffffffu, lsum0, 2);
    lsum1 += __shfl_xor_sync(0xffffffffu, lsum1, 1);
    lsum1 += __shfl_xor_sync(0xffffffffu, lsum1, 2);
    const float invl0 = 1.0f / lsum0;
    const float invl1 = 1.0f / lsum1;

    // =============== PHASE 2: attn + O = P V ===============
    float* attnb = outg + (size_t)OUT_ELEMS + (bh * SQ + (size_t)q0) * SQ;
    float* at0 = attnb + (size_t)r0 * SQ;
    float* at1 = attnb + (size_t)r1 * SQ;

    ku0 = cvt_f4(ks[tid]); ku1 = cvt_f4(ks[256 + tid]);
    uint2 vu0 = cvt_f4(vs[tid]), vu1 = cvt_f4(vs[256 + tid]);
    sts_u2(sm, SKH(0), tid, ku0);
    sts_u2(sm, SKH(0), 256 + tid, ku1);
    sts_u2(sm, SVH(0), tid, vu0);
    sts_u2(sm, SVH(0), 256 + tid, vu1);

    float O[8][4];
#pragma unroll
    for (int n = 0; n < 8; n++)
#pragma unroll
        for (int j = 0; j < 4; j++) O[n][j] = 0.0f;

    for (int t = 0; t < NTILES; t++) {
        const int cur = t & 1;
        unsigned w0 = mw0[t], w1 = mw1[t];
        if (t + 1 < NTILES) {
            ku0 = cvt_f4(ks[(t + 1) * 512 + tid]);
            ku1 = cvt_f4(ks[(t + 1) * 512 + 256 + tid]);
            vu0 = cvt_f4(vs[(t + 1) * 512 + tid]);
            vu1 = cvt_f4(vs[(t + 1) * 512 + 256 + tid]);
        }
        __syncthreads();

        // ---- S = Q_hi K_hi^T (identical arithmetic to phase 1) ----
        float S[4][4];
#pragma unroll
        for (int ng = 0; ng < 4; ng++)
#pragma unroll
            for (int j = 0; j < 4; j++) S[ng][j] = 0.0f;

#pragma unroll
        for (int kp = 0; kp < 2; kp++) {
#pragma unroll
            for (int ng = 0; ng < 4; ng++) {
                uint32_t kh[4];
                ldsm4(kh, sb + SKH(cur) + (uint32_t)(ng * 8) * RSTRIDE + kp * 64 + kfoff);
                mma16816(S[ng], kp ? q10 : q00, kh + 0);
                mma16816(S[ng], kp ? q11 : q01, kh + 2);
            }
        }

        // ---- p = mask*exp2(S)*invl; write attn; keep for PV ----
#pragma unroll
        for (int ng = 0; ng < 4; ng++) {
            int j = 8 * ng + 2 * t4;
            float e00 = ((w0 >> j) & 1u)       ? exp2f(S[ng][0]) * invl0 : 0.0f;
            float e01 = ((w0 >> (j + 1)) & 1u) ? exp2f(S[ng][1]) * invl0 : 0.0f;
            float e10 = ((w1 >> j) & 1u)       ? exp2f(S[ng][2]) * invl1 : 0.0f;
            float e11 = ((w1 >> (j + 1)) & 1u) ? exp2f(S[ng][3]) * invl1 : 0.0f;
            S[ng][0] = e00; S[ng][1] = e01; S[ng][2] = e10; S[ng][3] = e11;
            int col = t * KT + j;
            __stcs(reinterpret_cast<float2*>(&at0[col]), make_float2(e00, e01));
            __stcs(reinterpret_cast<float2*>(&at1[col]), make_float2(e10, e11));
        }

        uint32_t ahi[2][4];
#pragma unroll
        for (int f = 0; f < 2; f++) {
            ahi[f][0] = packh(S[2*f][0],   S[2*f][1]);
            ahi[f][1] = packh(S[2*f][2],   S[2*f][3]);
            ahi[f][2] = packh(S[2*f+1][0], S[2*f+1][1]);
            ahi[f][3] = packh(S[2*f+1][2], S[2*f+1][3]);
        }

        // ---- O += P_hi V_hi ----
#pragma unroll
        for (int n = 0; n < 8; n++) {
            uint32_t bh4[4];
            ldsm4t(bh4, sb + SVH(cur) + vfoff + 16 * n);
            mma16816(O[n], ahi[0], bh4 + 0);
            mma16816(O[n], ahi[1], bh4 + 2);
        }

        if (t + 1 < NTILES) {
            const int nxt = cur ^ 1;
            sts_u2(sm, SKH(nxt), tid, ku0);
            sts_u2(sm, SKH(nxt), 256 + tid, ku1);
            sts_u2(sm, SVH(nxt), tid, vu0);
            sts_u2(sm, SVH(nxt), 256 + tid, vu1);
        }
    }

    float* outb = outg + (bh * SQ + (size_t)q0) * DH;
#pragma unroll
    for (int n = 0; n < 8; n++) {
        int col = 8 * n + 2 * t4;
        *reinterpret_cast<float2*>(&outb[(size_t)r0 * DH + col]) = make_float2(O[n][0], O[n][1]);
        *reinterpret_cast<float2*>(&outb[(size_t)r1 * DH + col]) = make_float2(O[n][2], O[n][3]);
    }
}

extern "C" void kernel_launch(void* const* d_in, const int* in_sizes, int n_in,
                              void* d_out, int out_size) {
    const float* q   = (const float*)d_in[0];
    const float* k   = (const float*)d_in[1];
    const float* v   = (const float*)d_in[2];
    const int*   msk = (const int*)d_in[3];
    float* out = (float*)d_out;

    cudaFuncSetAttribute(sdpa_fused, cudaFuncAttributeMaxDynamicSharedMemorySize, SMEM_F);

    maskpack_kernel<<<(NB_ * SQ * SQ) / (128 * 8), 256>>>(msk);
    dim3 grid(SQ / 128, NH_, NB_);
    sdpa_fused<<<grid, 256, SMEM_F>>>(q, k, v, out);
}

// round 10
// speedup vs baseline: 1.0849x; 1.0849x over previous
#include <cuda_runtime.h>
#include <cuda_fp16.h>
#include <stdint.h>

#define SQ 2048
#define DH 64
#define NH_ 16
#define NB_ 4
#define KT 32
#define NTILES (SQ/KT)
#define OUT_ELEMS (NB_*NH_*SQ*DH)
#define RSTRIDE 144
#define QSCALE 0.18033688011112042f   // 0.125 * log2(e); exp(s) = exp2(S)

__device__ unsigned g_maskbits[(size_t)NB_ * SQ * (SQ / 32)];   // 2 MB
__device__ float    g_linv[(size_t)NB_ * NH_ * SQ];             // 512 KB

// pass0: K dbuf [0,9216); Q staged over [0,18432) in prologue
#define P0_KH(bf) ((bf)*4608)
#define SMEM_0 18432
// pass1: K dbuf [0,9216) + V dbuf [9216,18432); Q staged over [0,18432) in prologue
#define SKH(bf) ((bf)*4608)
#define SVH(bf) (9216 + (bf)*4608)
#define SMEM_1 18432

// ---------------- PTX helpers ----------------
__device__ __forceinline__ void ldsm4(uint32_t* r, uint32_t a) {
    asm volatile("ldmatrix.sync.aligned.m8n8.x4.shared.b16 {%0,%1,%2,%3}, [%4];"
                 : "=r"(r[0]), "=r"(r[1]), "=r"(r[2]), "=r"(r[3]) : "r"(a));
}
__device__ __forceinline__ void ldsm4t(uint32_t* r, uint32_t a) {
    asm volatile("ldmatrix.sync.aligned.m8n8.x4.trans.shared.b16 {%0,%1,%2,%3}, [%4];"
                 : "=r"(r[0]), "=r"(r[1]), "=r"(r[2]), "=r"(r[3]) : "r"(a));
}
__device__ __forceinline__ void mma16816(float* c, const uint32_t* a, const uint32_t* b) {
    asm volatile("mma.sync.aligned.m16n8k16.row.col.f32.f16.f16.f32 "
                 "{%0,%1,%2,%3}, {%4,%5,%6,%7}, {%8,%9}, {%0,%1,%2,%3};"
                 : "+f"(c[0]), "+f"(c[1]), "+f"(c[2]), "+f"(c[3])
                 : "r"(a[0]), "r"(a[1]), "r"(a[2]), "r"(a[3]), "r"(b[0]), "r"(b[1]));
}
__device__ __forceinline__ uint32_t packh(float x, float y) {
    __half2 h = __halves2half2(__float2half_rn(x), __float2half_rn(y));
    return *reinterpret_cast<uint32_t*>(&h);
}
__device__ __forceinline__ void sts_f4h(char* sm, int off, int lin, float4 x) {
    uint32_t a = (uint32_t)(lin >> 4) * RSTRIDE + (uint32_t)(lin & 15) * 8;
    *reinterpret_cast<uint2*>(sm + off + a) = make_uint2(packh(x.x, x.y), packh(x.z, x.w));
}

// ---------------- mask bit-pack ----------------
__global__ void maskpack_kernel(const int* __restrict__ mask) {
    int gwarp = blockIdx.x * 8 + (threadIdx.x >> 5);
    int lane = threadIdx.x & 31;
    size_t base = (size_t)gwarp * 128;
    unsigned b0 = __ballot_sync(0xffffffffu, mask[base + lane] != 0);
    unsigned b1 = __ballot_sync(0xffffffffu, mask[base + 32 + lane] != 0);
    unsigned b2 = __ballot_sync(0xffffffffu, mask[base + 64 + lane] != 0);
    unsigned b3 = __ballot_sync(0xffffffffu, mask[base + 96 + lane] != 0);
    if (lane == 0)
        *reinterpret_cast<uint4*>(&g_maskbits[(size_t)gwarp * 4]) = make_uint4(b0, b1, b2, b3);
}

// ---------------- shared prologue: stage Q -> smem, ldsm to regs, release ----------------
__device__ __forceinline__ void load_q_frags(char* sm, uint32_t sb, const float* qb,
                                             int tid, int warp, int lane,
                                             uint32_t* q00, uint32_t* q01,
                                             uint32_t* q10, uint32_t* q11)
{
#pragma unroll
    for (int i = 0; i < 8; i++) {
        int lin = i * 256 + tid;
        float4 x = reinterpret_cast<const float4*>(qb)[lin];
        x.x *= QSCALE; x.y *= QSCALE; x.z *= QSCALE; x.w *= QSCALE;
        sts_f4h(sm, 0, lin, x);
    }
    __syncthreads();
    const uint32_t qHaddr = sb + (uint32_t)(warp * 16 + (lane & 15)) * RSTRIDE
                          + (uint32_t)(lane >> 4) * 16;
    ldsm4(q00, qHaddr);
    ldsm4(q01, qHaddr + 32);
    ldsm4(q10, qHaddr + 64);
    ldsm4(q11, qHaddr + 96);
    __syncthreads();   // Q staging consumed; smem free for K/V buffers
}

// ---------------- pass0: lsum via single-term fp16 QK ----------------
__global__ __launch_bounds__(256, 2)
void sdpa_pass0(const float* __restrict__ qg, const float* __restrict__ kg)
{
    extern __shared__ char sm[];
    const uint32_t sb = (uint32_t)__cvta_generic_to_shared(sm);
    const int tid = threadIdx.x, warp = tid >> 5, lane = tid & 31;
    const int g = lane >> 2, t4 = lane & 3;
    const int qt = blockIdx.x, h = blockIdx.y, b = blockIdx.z;
    const int q0 = qt * 128;
    const size_t bh = (size_t)(b * NH_ + h);
    const float* qb = qg + (bh * SQ + (size_t)q0) * DH;
    const float* kb = kg + bh * SQ * DH;
    const int r0 = warp * 16 + g, r1 = r0 + 8;

    uint32_t q00[4], q01[4], q10[4], q11[4];
    load_q_frags(sm, sb, qb, tid, warp, lane, q00, q01, q10, q11);

    float4 pk0 = reinterpret_cast<const float4*>(kb)[tid];
    float4 pk1 = reinterpret_cast<const float4*>(kb)[256 + tid];
    sts_f4h(sm, P0_KH(0), tid, pk0);
    sts_f4h(sm, P0_KH(0), 256 + tid, pk1);

    float lsum0 = 0.0f, lsum1 = 0.0f;
    const uint32_t kfoff = (uint32_t)(lane & 7) * RSTRIDE + (uint32_t)(lane >> 3) * 16;
    const unsigned* mw0 = &g_maskbits[((size_t)b * SQ + q0 + r0) * (SQ / 32)];
    const unsigned* mw1 = &g_maskbits[((size_t)b * SQ + q0 + r1) * (SQ / 32)];

    for (int t = 0; t < NTILES; t++) {
        const int cur = t & 1;
        unsigned w0 = mw0[t], w1 = mw1[t];
        if (t + 1 < NTILES) {
            const float4* ks = reinterpret_cast<const float4*>(kb + (size_t)(t + 1) * KT * DH);
            pk0 = ks[tid]; pk1 = ks[256 + tid];
        }
        __syncthreads();

        float S[4][4];
#pragma unroll
        for (int ng = 0; ng < 4; ng++)
#pragma unroll
            for (int j = 0; j < 4; j++) S[ng][j] = 0.0f;

#pragma unroll
        for (int kp = 0; kp < 2; kp++) {
#pragma unroll
            for (int ng = 0; ng < 4; ng++) {
                uint32_t kh[4];
                ldsm4(kh, sb + P0_KH(cur) + (uint32_t)(ng * 8) * RSTRIDE + kp * 64 + kfoff);
                mma16816(S[ng], kp ? q10 : q00, kh + 0);
                mma16816(S[ng], kp ? q11 : q01, kh + 2);
            }
        }

#pragma unroll
        for (int ng = 0; ng < 4; ng++) {
            int j = 8 * ng + 2 * t4;
            lsum0 += (((w0 >> j) & 1u)       ? exp2f(S[ng][0]) : 0.0f)
                   + (((w0 >> (j + 1)) & 1u) ? exp2f(S[ng][1]) : 0.0f);
            lsum1 += (((w1 >> j) & 1u)       ? exp2f(S[ng][2]) : 0.0f)
                   + (((w1 >> (j + 1)) & 1u) ? exp2f(S[ng][3]) : 0.0f);
        }

        if (t + 1 < NTILES) {
            const int nxt = cur ^ 1;
            sts_f4h(sm, P0_KH(nxt), tid, pk0);
            sts_f4h(sm, P0_KH(nxt), 256 + tid, pk1);
        }
    }

    lsum0 += __shfl_xor_sync(0xffffffffu, lsum0, 1);
    lsum0 += __shfl_xor_sync(0xffffffffu, lsum0, 2);
    lsum1 += __shfl_xor_sync(0xffffffffu, lsum1, 1);
    lsum1 += __shfl_xor_sync(0xffffffffu, lsum1, 2);
    if (t4 == 0) {
        g_linv[bh * SQ + q0 + r0] = 1.0f / lsum0;
        g_linv[bh * SQ + q0 + r1] = 1.0f / lsum1;
    }
}

// ---------------- pass1: QK 1-term; O += P_hi V_hi; attn = p*invl ----------------
__global__ __launch_bounds__(256, 2)
void sdpa_pass1(const float* __restrict__ qg, const float* __restrict__ kg,
                const float* __restrict__ vg, float* __restrict__ outg)
{
    extern __shared__ char sm[];
    const uint32_t sb = (uint32_t)__cvta_generic_to_shared(sm);
    const int tid = threadIdx.x, warp = tid >> 5, lane = tid & 31;
    const int g = lane >> 2, t4 = lane & 3;
    const int qt = blockIdx.x, h = blockIdx.y, b = blockIdx.z;
    const int q0 = qt * 128;
    const size_t bh = (size_t)(b * NH_ + h);
    const float* qb = qg + (bh * SQ + (size_t)q0) * DH;
    const float* kb = kg + bh * SQ * DH;
    const float* vb = vg + bh * SQ * DH;
    const int r0 = warp * 16 + g, r1 = r0 + 8;

    const float invl0 = g_linv[bh * SQ + q0 + r0];
    const float invl1 = g_linv[bh * SQ + q0 + r1];

    uint32_t q00[4], q01[4], q10[4], q11[4];
    load_q_frags(sm, sb, qb, tid, warp, lane, q00, q01, q10, q11);

    float4 pk0 = reinterpret_cast<const float4*>(kb)[tid];
    float4 pk1 = reinterpret_cast<const float4*>(kb)[256 + tid];
    float4 pv0 = reinterpret_cast<const float4*>(vb)[tid];
    float4 pv1 = reinterpret_cast<const float4*>(vb)[256 + tid];
    sts_f4h(sm, SKH(0), tid, pk0);
    sts_f4h(sm, SKH(0), 256 + tid, pk1);
    sts_f4h(sm, SVH(0), tid, pv0);
    sts_f4h(sm, SVH(0), 256 + tid, pv1);

    float O[8][4];
#pragma unroll
    for (int n = 0; n < 8; n++)
#pragma unroll
        for (int j = 0; j < 4; j++) O[n][j] = 0.0f;

    const uint32_t kfoff = (uint32_t)(lane & 7) * RSTRIDE + (uint32_t)(lane >> 3) * 16;
    const uint32_t vfoff = (uint32_t)(8 * (lane >> 3) + (lane & 7)) * RSTRIDE;
    const unsigned* mw0 = &g_maskbits[((size_t)b * SQ + q0 + r0) * (SQ / 32)];
    const unsigned* mw1 = &g_maskbits[((size_t)b * SQ + q0 + r1) * (SQ / 32)];
    float* attnb = outg + (size_t)OUT_ELEMS + (bh * SQ + (size_t)q0) * SQ;
    float* at0 = attnb + (size_t)r0 * SQ;
    float* at1 = attnb + (size_t)r1 * SQ;

    for (int t = 0; t < NTILES; t++) {
        const int cur = t & 1;
        unsigned w0 = mw0[t], w1 = mw1[t];
        if (t + 1 < NTILES) {
            const float4* ks = reinterpret_cast<const float4*>(kb + (size_t)(t + 1) * KT * DH);
            const float4* vs = reinterpret_cast<const float4*>(vb + (size_t)(t + 1) * KT * DH);
            pk0 = ks[tid]; pk1 = ks[256 + tid];
            pv0 = vs[tid]; pv1 = vs[256 + tid];
        }
        __syncthreads();

        // ---- S = Q_hi K_hi^T (identical arithmetic to pass0) ----
        float S[4][4];
#pragma unroll
        for (int ng = 0; ng < 4; ng++)
#pragma unroll
            for (int j = 0; j < 4; j++) S[ng][j] = 0.0f;

#pragma unroll
        for (int kp = 0; kp < 2; kp++) {
#pragma unroll
            for (int ng = 0; ng < 4; ng++) {
                uint32_t kh[4];
                ldsm4(kh, sb + SKH(cur) + (uint32_t)(ng * 8) * RSTRIDE + kp * 64 + kfoff);
                mma16816(S[ng], kp ? q10 : q00, kh + 0);
                mma16816(S[ng], kp ? q11 : q01, kh + 2);
            }
        }

        // ---- p = mask*exp2(S)*invl ----
#pragma unroll
        for (int ng = 0; ng < 4; ng++) {
            int j = 8 * ng + 2 * t4;
            S[ng][0] = ((w0 >> j) & 1u)       ? exp2f(S[ng][0]) * invl0 : 0.0f;
            S[ng][1] = ((w0 >> (j + 1)) & 1u) ? exp2f(S[ng][1]) * invl0 : 0.0f;
            S[ng][2] = ((w1 >> j) & 1u)       ? exp2f(S[ng][2]) * invl1 : 0.0f;
            S[ng][3] = ((w1 >> (j + 1)) & 1u) ? exp2f(S[ng][3]) * invl1 : 0.0f;
        }

        // ---- pack + PV MMA first (keep tensor pipe fed) ----
        uint32_t ahi[2][4];
#pragma unroll
        for (int f = 0; f < 2; f++) {
            ahi[f][0] = packh(S[2*f][0],   S[2*f][1]);
            ahi[f][1] = packh(S[2*f][2],   S[2*f][3]);
            ahi[f][2] = packh(S[2*f+1][0], S[2*f+1][1]);
            ahi[f][3] = packh(S[2*f+1][2], S[2*f+1][3]);
        }
#pragma unroll
        for (int n = 0; n < 8; n++) {
            uint32_t bh4[4];
            ldsm4t(bh4, sb + SVH(cur) + vfoff + 16 * n);
            mma16816(O[n], ahi[0], bh4 + 0);
            mma16816(O[n], ahi[1], bh4 + 2);
        }

        // ---- attn writeback after MMA issue ----
#pragma unroll
        for (int ng = 0; ng < 4; ng++) {
            int col = t * KT + 8 * ng + 2 * t4;
            __stcs(reinterpret_cast<float2*>(&at0[col]), make_float2(S[ng][0], S[ng][1]));
            __stcs(reinterpret_cast<float2*>(&at1[col]), make_float2(S[ng][2], S[ng][3]));
        }

        if (t + 1 < NTILES) {
            const int nxt = cur ^ 1;
            sts_f4h(sm, SKH(nxt), tid, pk0);
            sts_f4h(sm, SKH(nxt), 256 + tid, pk1);
            sts_f4h(sm, SVH(nxt), tid, pv0);
            sts_f4h(sm, SVH(nxt), 256 + tid, pv1);
        }
    }

    float* outb = outg + (bh * SQ + (size_t)q0) * DH;
#pragma unroll
    for (int n = 0; n < 8; n++) {
        int col = 8 * n + 2 * t4;
        *reinterpret_cast<float2*>(&outb[(size_t)r0 * DH + col]) = make_float2(O[n][0], O[n][1]);
        *reinterpret_cast<float2*>(&outb[(size_t)r1 * DH + col]) = make_float2(O[n][2], O[n][3]);
    }
}

extern "C" void kernel_launch(void* const* d_in, const int* in_sizes, int n_in,
                              void* d_out, int out_size) {
    const float* q   = (const float*)d_in[0];
    const float* k   = (const float*)d_in[1];
    const float* v   = (const float*)d_in[2];
    const int*   msk = (const int*)d_in[3];
    float* out = (float*)d_out;

    cudaFuncSetAttribute(sdpa_pass0, cudaFuncAttributeMaxDynamicSharedMemorySize, SMEM_0);
    cudaFuncSetAttribute(sdpa_pass1, cudaFuncAttributeMaxDynamicSharedMemorySize, SMEM_1);

    maskpack_kernel<<<(NB_ * SQ * SQ) / (128 * 8), 256>>>(msk);
    dim3 grid(SQ / 128, NH_, NB_);
    sdpa_pass0<<<grid, 256, SMEM_0>>>(q, k);
    sdpa_pass1<<<grid, 256, SMEM_1>>>(q, k, v, out);
}